// round 1
// baseline (speedup 1.0000x reference)
#include <cuda_runtime.h>
#include <math.h>

#define BB 64
#define SS 512
#define BS (BB*SS)
#define LL 16
#define WD 200
#define CD 30
#define FN 4
#define CF 120
#define KW 3
#define DD 320
#define HH 256
#define G4 1024
#define TT 17
#define LC 14

// ---------------- static scratch (no allocs allowed) ----------------
__device__ float d_z[BS * DD];                    // [B*S, 320]
__device__ float d_gx[2][(size_t)SS * BB * G4];   // [dir][S,B,1024]
__device__ float d_hs[2][(size_t)SS * BB * HH];   // [dir][S,B,256]
__device__ float d_hcur[2][2][BB * HH];           // [dir][parity][B,256]
__device__ float d_emis[(size_t)BS * TT];         // [B,S,17]
__device__ float d_nd[BB];
__device__ int   d_ctr[16];

__device__ __forceinline__ int acq_load(const int* p) {
    int v;
    asm volatile("ld.global.acquire.gpu.b32 %0,[%1];" : "=r"(v) : "l"(p) : "memory");
    return v;
}
__device__ __forceinline__ float sigf(float x) { return 1.0f / (1.0f + expf(-x)); }

// ---------------- init ----------------
__global__ void k_init() {
    int t = threadIdx.x;
    if (t < 16) d_ctr[t] = 0;
}

// ---------------- embeddings + char CNN + concat ----------------
__global__ void __launch_bounds__(128) k_embed(const int* __restrict__ tok,
                                               const int* __restrict__ ctok,
                                               const float* __restrict__ wemb,
                                               const float* __restrict__ cemb,
                                               const float* __restrict__ convw,
                                               const float* __restrict__ convb) {
    int w = blockIdx.x;  // word = b*S + s
    __shared__ float ce[LL][CD];
    __shared__ int cid[LL];
    int tid = threadIdx.x;
    if (tid < LL) cid[tid] = ctok[(size_t)w * LL + tid];
    __syncthreads();
    for (int i = tid; i < LL * CD; i += 128) {
        int l = i / CD, c = i % CD;
        ce[l][c] = cemb[cid[l] * CD + c];
    }
    __syncthreads();
    if (tid < CF) {
        int o = tid, ic = o >> 2;
        float w0 = convw[o * 3 + 0], w1 = convw[o * 3 + 1], w2 = convw[o * 3 + 2];
        float m = -1e30f;
#pragma unroll
        for (int t = 0; t < LC; t++) {
            float v = ce[t][ic] * w0 + ce[t + 1][ic] * w1 + ce[t + 2][ic] * w2;
            m = fmaxf(m, v);
        }
        d_z[(size_t)w * DD + WD + o] = m + convb[o];
    }
    const float* wr = wemb + (size_t)tok[w] * WD;
    for (int j = tid; j < WD; j += 128) d_z[(size_t)w * DD + j] = wr[j];
}

// ---------------- input-side GEMM: z[BS,320] @ W^T[320,1024] + b -> gx[S,B,1024]
__global__ void __launch_bounds__(256) k_gemm_gx(const float* __restrict__ Wm,
                                                 const float* __restrict__ bias,
                                                 int dir) {
    const float* Z = d_z;
    float* out = d_gx[dir];
    int mBase = blockIdx.x * 64;
    int nBase = blockIdx.y * 64;
    __shared__ float As[16][64];
    __shared__ float Bs[16][64];
    int tid = threadIdx.x;
    int lr = tid >> 4;   // 0..15
    int lc = tid & 15;   // 0..15
    int ty = tid >> 4;
    int tx = tid & 15;
    float acc[4][4];
#pragma unroll
    for (int i = 0; i < 4; i++)
#pragma unroll
        for (int j = 0; j < 4; j++) acc[i][j] = 0.f;

    for (int k0 = 0; k0 < DD; k0 += 16) {
#pragma unroll
        for (int p = 0; p < 4; p++) {
            As[lc][lr + 16 * p] = Z[(size_t)(mBase + lr + 16 * p) * DD + k0 + lc];
            Bs[lc][lr + 16 * p] = Wm[(size_t)(nBase + lr + 16 * p) * DD + k0 + lc];
        }
        __syncthreads();
#pragma unroll
        for (int kk = 0; kk < 16; kk++) {
            float4 a = *(const float4*)&As[kk][ty * 4];
            float4 b = *(const float4*)&Bs[kk][tx * 4];
            acc[0][0] = fmaf(a.x, b.x, acc[0][0]); acc[0][1] = fmaf(a.x, b.y, acc[0][1]);
            acc[0][2] = fmaf(a.x, b.z, acc[0][2]); acc[0][3] = fmaf(a.x, b.w, acc[0][3]);
            acc[1][0] = fmaf(a.y, b.x, acc[1][0]); acc[1][1] = fmaf(a.y, b.y, acc[1][1]);
            acc[1][2] = fmaf(a.y, b.z, acc[1][2]); acc[1][3] = fmaf(a.y, b.w, acc[1][3]);
            acc[2][0] = fmaf(a.z, b.x, acc[2][0]); acc[2][1] = fmaf(a.z, b.y, acc[2][1]);
            acc[2][2] = fmaf(a.z, b.z, acc[2][2]); acc[2][3] = fmaf(a.z, b.w, acc[2][3]);
            acc[3][0] = fmaf(a.w, b.x, acc[3][0]); acc[3][1] = fmaf(a.w, b.y, acc[3][1]);
            acc[3][2] = fmaf(a.w, b.z, acc[3][2]); acc[3][3] = fmaf(a.w, b.w, acc[3][3]);
        }
        __syncthreads();
    }
    float bq[4];
#pragma unroll
    for (int j = 0; j < 4; j++) bq[j] = bias[nBase + tx * 4 + j];
#pragma unroll
    for (int i = 0; i < 4; i++) {
        int m = mBase + ty * 4 + i;
        int b = m >> 9, s = m & 511;
        size_t ro = ((size_t)s * BB + b) * (size_t)G4 + nBase + tx * 4;
        float4 o4;
        o4.x = acc[i][0] + bq[0];
        o4.y = acc[i][1] + bq[1];
        o4.z = acc[i][2] + bq[2];
        o4.w = acc[i][3] + bq[3];
        *(float4*)&out[ro] = o4;
    }
}

// ---------------- BiLSTM: 128 co-resident CTAs, global barrier per step ----------------
// blk = ((dir*8 + bg)*8 + slice); each CTA: 8 batch rows, 128 gate rows (32 k's x 4 gates)
__global__ void __launch_bounds__(128, 1) k_lstm(const float* __restrict__ whf,
                                                 const float* __restrict__ whb) {
    int blk = blockIdx.x;
    int slice = blk & 7;
    int grp = blk >> 3;        // 0..15
    int dir = grp >> 3;
    int bg = grp & 7;
    const float* Wd = dir ? whb : whf;
    int tid = threadIdx.x;
    int gt = tid >> 5;         // gate type 0..3 (i,f,g,o)
    int kl = tid & 31;
    int ks = slice * 32;
    int gr = gt * 256 + ks + kl;  // global gate row in [0,1024)
    const float* wrow = Wd + (size_t)gr * HH;
    const float* gxp = d_gx[dir];
    float* hsp = d_hs[dir];
    int b0 = bg * 8;

    __shared__ float h_sm[8 * HH];
    __shared__ float g_sm[4 * 32 * 8];
    __shared__ float c_sm[32 * 8];
    for (int i = tid; i < 256; i += 128) c_sm[i] = 0.f;
    __syncthreads();

    for (int s = 0; s < SS; s++) {
        int t = dir ? (SS - 1 - s) : s;
        const float* gxr = gxp + ((size_t)t * BB + b0) * G4 + gr;
        float acc[8];
#pragma unroll
        for (int b = 0; b < 8; b++) acc[b] = __ldg(gxr + (size_t)b * G4);

        if (s > 0) {
            if (tid == 0) {
                int tgt = 8 * s;
                while (acq_load(&d_ctr[grp]) < tgt) {}
            }
            __syncthreads();
            const float* hg = d_hcur[dir][(s - 1) & 1] + b0 * HH;
            for (int i = tid; i < 8 * HH; i += 128) h_sm[i] = __ldcg(hg + i);
            __syncthreads();
#pragma unroll 2
            for (int kk = 0; kk < HH; kk += 4) {
                float4 w4 = *(const float4*)(wrow + kk);
#pragma unroll
                for (int b = 0; b < 8; b++) {
                    float4 h4 = *(const float4*)(h_sm + b * HH + kk);
                    acc[b] = fmaf(w4.x, h4.x, acc[b]);
                    acc[b] = fmaf(w4.y, h4.y, acc[b]);
                    acc[b] = fmaf(w4.z, h4.z, acc[b]);
                    acc[b] = fmaf(w4.w, h4.w, acc[b]);
                }
            }
        }
#pragma unroll
        for (int b = 0; b < 8; b++) g_sm[(gt * 32 + kl) * 8 + b] = acc[b];
        __syncthreads();

        float* hw = d_hcur[dir][s & 1];
#pragma unroll
        for (int r = 0; r < 2; r++) {
            int task = tid + r * 128;
            int b = task >> 5;
            int k = task & 31;
            float gi = g_sm[(0 * 32 + k) * 8 + b];
            float gf = g_sm[(1 * 32 + k) * 8 + b];
            float gg = g_sm[(2 * 32 + k) * 8 + b];
            float go = g_sm[(3 * 32 + k) * 8 + b];
            float c = c_sm[k * 8 + b];
            float cn = sigf(gf) * c + sigf(gi) * tanhf(gg);
            float hv = sigf(go) * tanhf(cn);
            c_sm[k * 8 + b] = cn;
            int bgl = b0 + b;
            __stcg(&hw[bgl * HH + ks + k], hv);
            hsp[((size_t)t * BB + bgl) * HH + ks + k] = hv;
        }
        __threadfence();
        __syncthreads();
        if (tid == 0) atomicAdd(&d_ctr[grp], 1);
    }
}

// ---------------- emissions: concat(hs_f, hs_b) @ cls_w^T + cls_b ----------------
__global__ void __launch_bounds__(256) k_emis(const float* __restrict__ clsw,
                                              const float* __restrict__ clsb) {
    int w = blockIdx.x;             // b*S + s
    int b = w >> 9, s = w & 511;
    __shared__ float sm[512];
    int tid = threadIdx.x;
    sm[tid] = d_hs[0][((size_t)s * BB + b) * HH + tid];
    sm[256 + tid] = d_hs[1][((size_t)s * BB + b) * HH + tid];
    __syncthreads();
    if (tid < 160) {
        int o = tid >> 3, part = tid & 7;
        bool valid = (o < TT);
        float sum = 0.f;
        if (valid) {
            const float* cw = clsw + (size_t)o * 512 + part * 64;
            const float* hv = sm + part * 64;
#pragma unroll 8
            for (int j = 0; j < 64; j++) sum = fmaf(cw[j], hv[j], sum);
        }
        sum += __shfl_down_sync(0xffffffffu, sum, 4);
        sum += __shfl_down_sync(0xffffffffu, sum, 2);
        sum += __shfl_down_sync(0xffffffffu, sum, 1);
        if (valid && part == 0) d_emis[(size_t)w * TT + o] = sum + clsb[o];
    }
}

// ---------------- CRF loss (forward algorithm), per-batch block ----------------
__global__ void __launch_bounds__(32) k_crf_loss(const int* __restrict__ labels,
                                                 const int* __restrict__ mask,
                                                 const float* __restrict__ startt,
                                                 const float* __restrict__ endt,
                                                 const float* __restrict__ trans) {
    int b = blockIdx.x;
    int ln = threadIdx.x;
    __shared__ float tr[TT * TT];
    __shared__ float al[TT];
    for (int i = ln; i < TT * TT; i += 32) tr[i] = trans[i];
    __syncwarp();

    // numerator partials
    float part = 0.f;
    for (int s = ln; s < SS; s += 32) {
        int tg = labels[(size_t)b * SS + s];
        float mf = (float)mask[(size_t)b * SS + s];
        part += d_emis[((size_t)b * SS + s) * TT + tg] * mf;
        if (s >= 1) {
            int tp = labels[(size_t)b * SS + s - 1];
            part += tr[tp * TT + tg] * mf;
        }
    }
#pragma unroll
    for (int off = 16; off > 0; off >>= 1) part += __shfl_down_sync(0xffffffffu, part, off);
    float num = 0.f;
    if (ln == 0) {
        num = part + startt[labels[(size_t)b * SS]];
        int cnt = 0;
        for (int s = 0; s < SS; s++) cnt += mask[(size_t)b * SS + s];
        num += endt[labels[(size_t)b * SS + cnt - 1]];
    }

    // forward algorithm
    if (ln < TT) al[ln] = startt[ln] + d_emis[((size_t)b * SS) * TT + ln];
    __syncwarp();
    for (int s = 1; s < SS; s++) {
        int m = mask[(size_t)b * SS + s];
        float nv = 0.f;
        if (ln < TT) {
            float v[TT];
            float mx = -1e30f;
#pragma unroll
            for (int i = 0; i < TT; i++) {
                v[i] = al[i] + tr[i * TT + ln];
                mx = fmaxf(mx, v[i]);
            }
            float sum = 0.f;
#pragma unroll
            for (int i = 0; i < TT; i++) sum += expf(v[i] - mx);
            nv = mx + logf(sum) + d_emis[((size_t)b * SS + s) * TT + ln];
        }
        __syncwarp();
        if (ln < TT && m > 0) al[ln] = nv;
        __syncwarp();
    }
    if (ln == 0) {
        float mx = -1e30f;
        for (int j = 0; j < TT; j++) mx = fmaxf(mx, al[j] + endt[j]);
        float sum = 0.f;
        for (int j = 0; j < TT; j++) sum += expf(al[j] + endt[j] - mx);
        d_nd[b] = num - (mx + logf(sum));
    }
}

// ---------------- CRF Viterbi decode, per-batch block ----------------
__global__ void __launch_bounds__(32) k_decode(const int* __restrict__ mask,
                                               const float* __restrict__ startt,
                                               const float* __restrict__ endt,
                                               const float* __restrict__ trans,
                                               float* __restrict__ tok_out) {
    int b = blockIdx.x;
    int ln = threadIdx.x;
    __shared__ float tr[TT * TT];
    __shared__ float al[TT];
    __shared__ unsigned char bp[SS - 1][TT];
    for (int i = ln; i < TT * TT; i += 32) tr[i] = trans[i];
    if (ln < TT) al[ln] = startt[ln] + d_emis[((size_t)b * SS) * TT + ln];
    __syncwarp();
    for (int s = 1; s < SS; s++) {
        int m = mask[(size_t)b * SS + s];
        float nv = 0.f;
        int arg = 0;
        if (ln < TT) {
            float mx = -1e30f;
#pragma unroll
            for (int i = 0; i < TT; i++) {
                float v = al[i] + tr[i * TT + ln];
                if (v > mx) { mx = v; arg = i; }   // first-max semantics
            }
            nv = mx + d_emis[((size_t)b * SS + s) * TT + ln];
        }
        __syncwarp();
        if (ln < TT) {
            if (m > 0) { al[ln] = nv; bp[s - 1][ln] = (unsigned char)arg; }
            else bp[s - 1][ln] = (unsigned char)ln;
        }
        __syncwarp();
    }
    if (ln == 0) {
        float mx = -1e30f;
        int lt = 0;
        for (int j = 0; j < TT; j++) {
            float v = al[j] + endt[j];
            if (v > mx) { mx = v; lt = j; }
        }
        tok_out[(size_t)b * SS + (SS - 1)] = (float)lt;
        int tg = lt;
        for (int s = SS - 2; s >= 0; s--) {
            tg = bp[s][tg];
            tok_out[(size_t)b * SS + s] = (float)tg;
        }
    }
}

// ---------------- final loss reduce ----------------
__global__ void __launch_bounds__(64) k_final(float* __restrict__ out) {
    int tid = threadIdx.x;
    float v = d_nd[tid];
#pragma unroll
    for (int off = 16; off > 0; off >>= 1) v += __shfl_down_sync(0xffffffffu, v, off);
    __shared__ float w[2];
    if ((tid & 31) == 0) w[tid >> 5] = v;
    __syncthreads();
    if (tid == 0) out[0] = -(w[0] + w[1]) / (float)BB;
}

// ---------------- launch ----------------
extern "C" void kernel_launch(void* const* d_in, const int* in_sizes, int n_in,
                              void* d_out, int out_size) {
    const int* tok     = (const int*)d_in[0];
    const int* ctok    = (const int*)d_in[1];
    const int* labels  = (const int*)d_in[2];
    const int* amask   = (const int*)d_in[3];
    const float* wemb  = (const float*)d_in[4];
    const float* cemb  = (const float*)d_in[5];
    const float* convw = (const float*)d_in[6];
    const float* convb = (const float*)d_in[7];
    const float* wihf  = (const float*)d_in[8];
    const float* whhf  = (const float*)d_in[9];
    const float* bf    = (const float*)d_in[10];
    const float* wihb  = (const float*)d_in[11];
    const float* whhb  = (const float*)d_in[12];
    const float* bb    = (const float*)d_in[13];
    const float* clsw  = (const float*)d_in[14];
    const float* clsb  = (const float*)d_in[15];
    const float* startt = (const float*)d_in[16];
    const float* endt   = (const float*)d_in[17];
    const float* trans  = (const float*)d_in[18];
    float* out = (float*)d_out;
    int tok_off = out_size - BB * SS;
    if (tok_off < 0) tok_off = 0;

    k_init<<<1, 32>>>();
    k_embed<<<BS, 128>>>(tok, ctok, wemb, cemb, convw, convb);
    dim3 gg(BS / 64, G4 / 64);
    k_gemm_gx<<<gg, 256>>>(wihf, bf, 0);
    k_gemm_gx<<<gg, 256>>>(wihb, bb, 1);
    k_lstm<<<128, 128>>>(whhf, whhb);
    k_emis<<<BS, 256>>>(clsw, clsb);
    k_crf_loss<<<BB, 32>>>(labels, amask, startt, endt, trans);
    k_decode<<<BB, 32>>>(amask, startt, endt, trans, out + tok_off);
    k_final<<<1, 64>>>(out);
}

// round 2
// speedup vs baseline: 1.3311x; 1.3311x over previous
#include <cuda_runtime.h>
#include <math.h>

#define BB 64
#define SS 512
#define BS (BB*SS)
#define LL 16
#define WD 200
#define CD 30
#define FN 4
#define CF 120
#define KW 3
#define DD 320
#define HH 256
#define G4 1024
#define TT 17
#define LC 14

// ---------------- static scratch (no allocs allowed) ----------------
__device__ float d_z[BS * DD];                    // [B*S, 320]
__device__ float d_gx[2][(size_t)SS * BB * G4];   // [dir][S,B,1024]
__device__ float d_hs[2][(size_t)SS * BB * HH];   // [dir][S,B,256]
__device__ float d_hcur[2][2][BB * HH];           // [dir][parity][B,256]
__device__ float d_emis[(size_t)BS * TT];         // [B,S,17]
__device__ float d_nd[BB];
__device__ int   d_ctr[16];

__device__ __forceinline__ int acq_load(const int* p) {
    int v;
    asm volatile("ld.global.acquire.gpu.b32 %0,[%1];" : "=r"(v) : "l"(p) : "memory");
    return v;
}
__device__ __forceinline__ float sigf(float x) { return 1.0f / (1.0f + expf(-x)); }

// ---------------- init ----------------
__global__ void k_init() {
    int t = threadIdx.x;
    if (t < 16) d_ctr[t] = 0;
}

// ---------------- embeddings + char CNN + concat ----------------
__global__ void __launch_bounds__(128) k_embed(const int* __restrict__ tok,
                                               const int* __restrict__ ctok,
                                               const float* __restrict__ wemb,
                                               const float* __restrict__ cemb,
                                               const float* __restrict__ convw,
                                               const float* __restrict__ convb) {
    int w = blockIdx.x;  // word = b*S + s
    __shared__ float ce[LL][CD];
    __shared__ int cid[LL];
    int tid = threadIdx.x;
    if (tid < LL) cid[tid] = ctok[(size_t)w * LL + tid];
    __syncthreads();
    for (int i = tid; i < LL * CD; i += 128) {
        int l = i / CD, c = i % CD;
        ce[l][c] = cemb[cid[l] * CD + c];
    }
    __syncthreads();
    if (tid < CF) {
        int o = tid, ic = o >> 2;
        float w0 = convw[o * 3 + 0], w1 = convw[o * 3 + 1], w2 = convw[o * 3 + 2];
        float m = -1e30f;
#pragma unroll
        for (int t = 0; t < LC; t++) {
            float v = ce[t][ic] * w0 + ce[t + 1][ic] * w1 + ce[t + 2][ic] * w2;
            m = fmaxf(m, v);
        }
        d_z[(size_t)w * DD + WD + o] = m + convb[o];
    }
    const float* wr = wemb + (size_t)tok[w] * WD;
    for (int j = tid; j < WD; j += 128) d_z[(size_t)w * DD + j] = wr[j];
}

// ---------------- input-side GEMM: z[BS,320] @ W^T[320,1024] + b -> gx[S,B,1024]
// 128x64 tile, 256 threads, 8x4 microtile, conflict-light smem (pad 132/68)
__global__ void __launch_bounds__(256, 2) k_gemm_gx(const float* __restrict__ Wf,
                                                    const float* __restrict__ biasf,
                                                    const float* __restrict__ Wb,
                                                    const float* __restrict__ biasb) {
    int dir = blockIdx.z;
    const float* __restrict__ Wm = dir ? Wb : Wf;
    const float* __restrict__ bias = dir ? biasb : biasf;
    float* out = d_gx[dir];
    const float* __restrict__ Z = d_z;

    int mBase = blockIdx.x * 128;
    int nBase = blockIdx.y * 64;

    __shared__ float As[16][132];
    __shared__ float Bs[16][68];

    int tid = threadIdx.x;
    int ty = tid >> 4;   // 0..15  -> 8 output rows
    int tx = tid & 15;   // 0..15  -> 4 output cols

    float acc[8][4];
#pragma unroll
    for (int i = 0; i < 8; i++)
#pragma unroll
        for (int j = 0; j < 4; j++) acc[i][j] = 0.f;

    for (int k0 = 0; k0 < DD; k0 += 16) {
        // load A tile: 128 rows x 16 k = 512 float4, 2 per thread
#pragma unroll
        for (int r = 0; r < 2; r++) {
            int idx = tid + r * 256;
            int row = idx >> 2, kq = idx & 3;
            float4 v = *(const float4*)&Z[(size_t)(mBase + row) * DD + k0 + kq * 4];
            As[kq * 4 + 0][row] = v.x;
            As[kq * 4 + 1][row] = v.y;
            As[kq * 4 + 2][row] = v.z;
            As[kq * 4 + 3][row] = v.w;
        }
        // load B tile: 64 rows x 16 k = 256 float4, 1 per thread
        {
            int row = tid >> 2, kq = tid & 3;
            float4 v = *(const float4*)&Wm[(size_t)(nBase + row) * DD + k0 + kq * 4];
            Bs[kq * 4 + 0][row] = v.x;
            Bs[kq * 4 + 1][row] = v.y;
            Bs[kq * 4 + 2][row] = v.z;
            Bs[kq * 4 + 3][row] = v.w;
        }
        __syncthreads();
#pragma unroll
        for (int kk = 0; kk < 16; kk++) {
            float4 a0 = *(const float4*)&As[kk][ty * 8];
            float4 a1 = *(const float4*)&As[kk][ty * 8 + 4];
            float4 b0 = *(const float4*)&Bs[kk][tx * 4];
            float av[8] = {a0.x, a0.y, a0.z, a0.w, a1.x, a1.y, a1.z, a1.w};
            float bv[4] = {b0.x, b0.y, b0.z, b0.w};
#pragma unroll
            for (int i = 0; i < 8; i++)
#pragma unroll
                for (int j = 0; j < 4; j++)
                    acc[i][j] = fmaf(av[i], bv[j], acc[i][j]);
        }
        __syncthreads();
    }

    float bq[4];
#pragma unroll
    for (int j = 0; j < 4; j++) bq[j] = bias[nBase + tx * 4 + j];
#pragma unroll
    for (int i = 0; i < 8; i++) {
        int m = mBase + ty * 8 + i;
        int b = m >> 9, s = m & 511;
        size_t ro = ((size_t)s * BB + b) * (size_t)G4 + nBase + tx * 4;
        float4 o4;
        o4.x = acc[i][0] + bq[0];
        o4.y = acc[i][1] + bq[1];
        o4.z = acc[i][2] + bq[2];
        o4.w = acc[i][3] + bq[3];
        *(float4*)&out[ro] = o4;
    }
}

// ---------------- BiLSTM: 128 co-resident CTAs, global barrier per step ----------------
// blk = ((dir*8 + bg)*8 + slice); each CTA: 8 batch rows, 128 gate rows (32 k's x 4 gates)
__global__ void __launch_bounds__(128, 1) k_lstm(const float* __restrict__ whf,
                                                 const float* __restrict__ whb) {
    int blk = blockIdx.x;
    int slice = blk & 7;
    int grp = blk >> 3;        // 0..15
    int dir = grp >> 3;
    int bg = grp & 7;
    const float* Wd = dir ? whb : whf;
    int tid = threadIdx.x;
    int gt = tid >> 5;         // gate type 0..3 (i,f,g,o)
    int kl = tid & 31;
    int ks = slice * 32;
    int gr = gt * 256 + ks + kl;  // global gate row in [0,1024)
    const float* wrow = Wd + (size_t)gr * HH;
    const float* gxp = d_gx[dir];
    float* hsp = d_hs[dir];
    int b0 = bg * 8;

    __shared__ float h_sm[8 * HH];
    __shared__ float g_sm[4 * 32 * 8];
    __shared__ float c_sm[32 * 8];
    for (int i = tid; i < 256; i += 128) c_sm[i] = 0.f;
    __syncthreads();

    for (int s = 0; s < SS; s++) {
        int t = dir ? (SS - 1 - s) : s;
        const float* gxr = gxp + ((size_t)t * BB + b0) * G4 + gr;
        float acc[8];
#pragma unroll
        for (int b = 0; b < 8; b++) acc[b] = __ldg(gxr + (size_t)b * G4);

        if (s > 0) {
            if (tid == 0) {
                int tgt = 8 * s;
                while (acq_load(&d_ctr[grp]) < tgt) {}
            }
            __syncthreads();
            const float* hg = d_hcur[dir][(s - 1) & 1] + b0 * HH;
            for (int i = tid; i < 8 * HH; i += 128) h_sm[i] = __ldcg(hg + i);
            __syncthreads();
#pragma unroll 2
            for (int kk = 0; kk < HH; kk += 4) {
                float4 w4 = *(const float4*)(wrow + kk);
#pragma unroll
                for (int b = 0; b < 8; b++) {
                    float4 h4 = *(const float4*)(h_sm + b * HH + kk);
                    acc[b] = fmaf(w4.x, h4.x, acc[b]);
                    acc[b] = fmaf(w4.y, h4.y, acc[b]);
                    acc[b] = fmaf(w4.z, h4.z, acc[b]);
                    acc[b] = fmaf(w4.w, h4.w, acc[b]);
                }
            }
        }
#pragma unroll
        for (int b = 0; b < 8; b++) g_sm[(gt * 32 + kl) * 8 + b] = acc[b];
        __syncthreads();

        float* hw = d_hcur[dir][s & 1];
#pragma unroll
        for (int r = 0; r < 2; r++) {
            int task = tid + r * 128;
            int b = task >> 5;
            int k = task & 31;
            float gi = g_sm[(0 * 32 + k) * 8 + b];
            float gf = g_sm[(1 * 32 + k) * 8 + b];
            float gg = g_sm[(2 * 32 + k) * 8 + b];
            float go = g_sm[(3 * 32 + k) * 8 + b];
            float c = c_sm[k * 8 + b];
            float cn = sigf(gf) * c + sigf(gi) * tanhf(gg);
            float hv = sigf(go) * tanhf(cn);
            c_sm[k * 8 + b] = cn;
            int bgl = b0 + b;
            __stcg(&hw[bgl * HH + ks + k], hv);
            hsp[((size_t)t * BB + bgl) * HH + ks + k] = hv;
        }
        __threadfence();
        __syncthreads();
        if (tid == 0) atomicAdd(&d_ctr[grp], 1);
    }
}

// ---------------- emissions: concat(hs_f, hs_b) @ cls_w^T + cls_b ----------------
// block caches cls_w in smem; warp per word; lane-strided conflict-free access
__global__ void __launch_bounds__(256) k_emis(const float* __restrict__ clsw,
                                              const float* __restrict__ clsb) {
    __shared__ float cw[TT * 512];
    __shared__ float cb[32];
    int tid = threadIdx.x;
    for (int i = tid; i < TT * 512; i += 256) cw[i] = clsw[i];
    if (tid < TT) cb[tid] = clsb[tid];
    __syncthreads();

    int warp = tid >> 5, lane = tid & 31;
    int w = blockIdx.x * 8 + warp;       // word = b*S + s
    int b = w >> 9, s = w & 511;
    const float* hf = d_hs[0] + ((size_t)s * BB + b) * HH;
    const float* hb = d_hs[1] + ((size_t)s * BB + b) * HH;
    float hv[16];
#pragma unroll
    for (int i = 0; i < 8; i++) {
        hv[i] = hf[lane + 32 * i];
        hv[8 + i] = hb[lane + 32 * i];
    }
#pragma unroll 1
    for (int o = 0; o < TT; o++) {
        const float* c0 = cw + o * 512;
        float sum = 0.f;
#pragma unroll
        for (int i = 0; i < 8; i++) {
            sum = fmaf(hv[i], c0[lane + 32 * i], sum);
            sum = fmaf(hv[8 + i], c0[256 + lane + 32 * i], sum);
        }
#pragma unroll
        for (int off = 16; off > 0; off >>= 1)
            sum += __shfl_down_sync(0xffffffffu, sum, off);
        if (lane == 0) d_emis[(size_t)w * TT + o] = sum + cb[o];
    }
}

// ---------------- CRF loss (forward algorithm), per-batch block ----------------
__global__ void __launch_bounds__(32) k_crf_loss(const int* __restrict__ labels,
                                                 const int* __restrict__ mask,
                                                 const float* __restrict__ startt,
                                                 const float* __restrict__ endt,
                                                 const float* __restrict__ trans) {
    int b = blockIdx.x;
    int ln = threadIdx.x;
    __shared__ float tr[TT * TT];
    __shared__ float al[TT];
    for (int i = ln; i < TT * TT; i += 32) tr[i] = trans[i];
    __syncwarp();

    // numerator partials
    float part = 0.f;
    for (int s = ln; s < SS; s += 32) {
        int tg = labels[(size_t)b * SS + s];
        float mf = (float)mask[(size_t)b * SS + s];
        part += d_emis[((size_t)b * SS + s) * TT + tg] * mf;
        if (s >= 1) {
            int tp = labels[(size_t)b * SS + s - 1];
            part += tr[tp * TT + tg] * mf;
        }
    }
#pragma unroll
    for (int off = 16; off > 0; off >>= 1) part += __shfl_down_sync(0xffffffffu, part, off);
    float num = 0.f;
    if (ln == 0) {
        num = part + startt[labels[(size_t)b * SS]];
        int cnt = 0;
        for (int s = 0; s < SS; s++) cnt += mask[(size_t)b * SS + s];
        num += endt[labels[(size_t)b * SS + cnt - 1]];
    }

    // forward algorithm
    if (ln < TT) al[ln] = startt[ln] + d_emis[((size_t)b * SS) * TT + ln];
    __syncwarp();
    for (int s = 1; s < SS; s++) {
        int m = mask[(size_t)b * SS + s];
        float nv = 0.f;
        if (ln < TT) {
            float v[TT];
            float mx = -1e30f;
#pragma unroll
            for (int i = 0; i < TT; i++) {
                v[i] = al[i] + tr[i * TT + ln];
                mx = fmaxf(mx, v[i]);
            }
            float sum = 0.f;
#pragma unroll
            for (int i = 0; i < TT; i++) sum += expf(v[i] - mx);
            nv = mx + logf(sum) + d_emis[((size_t)b * SS + s) * TT + ln];
        }
        __syncwarp();
        if (ln < TT && m > 0) al[ln] = nv;
        __syncwarp();
    }
    if (ln == 0) {
        float mx = -1e30f;
        for (int j = 0; j < TT; j++) mx = fmaxf(mx, al[j] + endt[j]);
        float sum = 0.f;
        for (int j = 0; j < TT; j++) sum += expf(al[j] + endt[j] - mx);
        d_nd[b] = num - (mx + logf(sum));
    }
}

// ---------------- CRF Viterbi decode, per-batch block ----------------
__global__ void __launch_bounds__(32) k_decode(const int* __restrict__ mask,
                                               const float* __restrict__ startt,
                                               const float* __restrict__ endt,
                                               const float* __restrict__ trans,
                                               float* __restrict__ tok_out) {
    int b = blockIdx.x;
    int ln = threadIdx.x;
    __shared__ float tr[TT * TT];
    __shared__ float al[TT];
    __shared__ unsigned char bp[SS - 1][TT];
    for (int i = ln; i < TT * TT; i += 32) tr[i] = trans[i];
    if (ln < TT) al[ln] = startt[ln] + d_emis[((size_t)b * SS) * TT + ln];
    __syncwarp();
    for (int s = 1; s < SS; s++) {
        int m = mask[(size_t)b * SS + s];
        float nv = 0.f;
        int arg = 0;
        if (ln < TT) {
            float mx = -1e30f;
#pragma unroll
            for (int i = 0; i < TT; i++) {
                float v = al[i] + tr[i * TT + ln];
                if (v > mx) { mx = v; arg = i; }   // first-max semantics
            }
            nv = mx + d_emis[((size_t)b * SS + s) * TT + ln];
        }
        __syncwarp();
        if (ln < TT) {
            if (m > 0) { al[ln] = nv; bp[s - 1][ln] = (unsigned char)arg; }
            else bp[s - 1][ln] = (unsigned char)ln;
        }
        __syncwarp();
    }
    if (ln == 0) {
        float mx = -1e30f;
        int lt = 0;
        for (int j = 0; j < TT; j++) {
            float v = al[j] + endt[j];
            if (v > mx) { mx = v; lt = j; }
        }
        tok_out[(size_t)b * SS + (SS - 1)] = (float)lt;
        int tg = lt;
        for (int s = SS - 2; s >= 0; s--) {
            tg = bp[s][tg];
            tok_out[(size_t)b * SS + s] = (float)tg;
        }
    }
}

// ---------------- final loss reduce ----------------
__global__ void __launch_bounds__(64) k_final(float* __restrict__ out) {
    int tid = threadIdx.x;
    float v = d_nd[tid];
#pragma unroll
    for (int off = 16; off > 0; off >>= 1) v += __shfl_down_sync(0xffffffffu, v, off);
    __shared__ float w[2];
    if ((tid & 31) == 0) w[tid >> 5] = v;
    __syncthreads();
    if (tid == 0) out[0] = -(w[0] + w[1]) / (float)BB;
}

// ---------------- launch ----------------
extern "C" void kernel_launch(void* const* d_in, const int* in_sizes, int n_in,
                              void* d_out, int out_size) {
    const int* tok     = (const int*)d_in[0];
    const int* ctok    = (const int*)d_in[1];
    const int* labels  = (const int*)d_in[2];
    const int* amask   = (const int*)d_in[3];
    const float* wemb  = (const float*)d_in[4];
    const float* cemb  = (const float*)d_in[5];
    const float* convw = (const float*)d_in[6];
    const float* convb = (const float*)d_in[7];
    const float* wihf  = (const float*)d_in[8];
    const float* whhf  = (const float*)d_in[9];
    const float* bf    = (const float*)d_in[10];
    const float* wihb  = (const float*)d_in[11];
    const float* whhb  = (const float*)d_in[12];
    const float* bb    = (const float*)d_in[13];
    const float* clsw  = (const float*)d_in[14];
    const float* clsb  = (const float*)d_in[15];
    const float* startt = (const float*)d_in[16];
    const float* endt   = (const float*)d_in[17];
    const float* trans  = (const float*)d_in[18];
    float* out = (float*)d_out;
    int tok_off = out_size - BB * SS;
    if (tok_off < 0) tok_off = 0;

    k_init<<<1, 32>>>();
    k_embed<<<BS, 128>>>(tok, ctok, wemb, cemb, convw, convb);
    dim3 gg(BS / 128, G4 / 64, 2);
    k_gemm_gx<<<gg, 256>>>(wihf, bf, wihb, bb);
    k_lstm<<<128, 128>>>(whhf, whhb);
    k_emis<<<BS / 8, 256>>>(clsw, clsb);
    k_crf_loss<<<BB, 32>>>(labels, amask, startt, endt, trans);
    k_decode<<<BB, 32>>>(amask, startt, endt, trans, out + tok_off);
    k_final<<<1, 64>>>(out);
}

// round 3
// speedup vs baseline: 1.4284x; 1.0731x over previous
#include <cuda_runtime.h>
#include <math.h>
#include <stdint.h>

#define BB 64
#define SS 512
#define BS (BB*SS)
#define LL 16
#define WD 200
#define CD 30
#define FN 4
#define CF 120
#define KW 3
#define DD 320
#define HH 256
#define G4 1024
#define TT 17
#define LC 14

// ---------------- static scratch (no allocs allowed) ----------------
__device__ float d_z[BS * DD];                    // [B*S, 320]
__device__ float d_gx[2][(size_t)SS * BB * G4];   // [dir][S,B,1024]
__device__ float d_hs[2][(size_t)SS * BB * HH];   // [dir][S,B,256]
__device__ float d_emis[(size_t)BS * TT];         // [B,S,17]
__device__ float d_nd[BB];

__device__ __forceinline__ float sigf(float x) { return 1.0f / (1.0f + expf(-x)); }

// ---- packed f32x2 helpers (sm_103a FFMA2) ----
__device__ __forceinline__ unsigned long long fdup(float w) {
    unsigned long long d;
    asm("mov.b64 %0, {%1, %1};" : "=l"(d) : "f"(w));
    return d;
}
__device__ __forceinline__ void ffma2(unsigned long long& a, unsigned long long x,
                                      unsigned long long y) {
    asm("fma.rn.f32x2 %0, %1, %2, %0;" : "+l"(a) : "l"(x), "l"(y));
}
__device__ __forceinline__ float2 unpk(unsigned long long a) {
    float2 f;
    asm("mov.b64 {%0, %1}, %2;" : "=f"(f.x), "=f"(f.y) : "l"(a));
    return f;
}
__device__ __forceinline__ unsigned int smem_u32(const void* p) {
    unsigned int a;
    asm("{ .reg .u64 t; cvta.to.shared.u64 t, %1; cvt.u32.u64 %0, t; }" : "=r"(a) : "l"(p));
    return a;
}
__device__ __forceinline__ unsigned int mapa_rank(unsigned int addr, int rank) {
    unsigned int r;
    asm("mapa.shared::cluster.u32 %0, %1, %2;" : "=r"(r) : "r"(addr), "r"(rank));
    return r;
}
__device__ __forceinline__ void st_cluster(unsigned int addr, unsigned int v) {
    asm volatile("st.shared::cluster.b32 [%0], %1;" :: "r"(addr), "r"(v) : "memory");
}

// ---------------- embeddings + char CNN + concat ----------------
__global__ void __launch_bounds__(128) k_embed(const int* __restrict__ tok,
                                               const int* __restrict__ ctok,
                                               const float* __restrict__ wemb,
                                               const float* __restrict__ cemb,
                                               const float* __restrict__ convw,
                                               const float* __restrict__ convb) {
    int w = blockIdx.x;  // word = b*S + s
    __shared__ float ce[LL][CD];
    __shared__ int cid[LL];
    int tid = threadIdx.x;
    if (tid < LL) cid[tid] = ctok[(size_t)w * LL + tid];
    __syncthreads();
    for (int i = tid; i < LL * CD; i += 128) {
        int l = i / CD, c = i % CD;
        ce[l][c] = cemb[cid[l] * CD + c];
    }
    __syncthreads();
    if (tid < CF) {
        int o = tid, ic = o >> 2;
        float w0 = convw[o * 3 + 0], w1 = convw[o * 3 + 1], w2 = convw[o * 3 + 2];
        float m = -1e30f;
#pragma unroll
        for (int t = 0; t < LC; t++) {
            float v = ce[t][ic] * w0 + ce[t + 1][ic] * w1 + ce[t + 2][ic] * w2;
            m = fmaxf(m, v);
        }
        d_z[(size_t)w * DD + WD + o] = m + convb[o];
    }
    const float* wr = wemb + (size_t)tok[w] * WD;
    for (int j = tid; j < WD; j += 128) d_z[(size_t)w * DD + j] = wr[j];
}

// ---------------- input-side GEMM with FFMA2: z[BS,320] @ W^T -> gx ----------------
__global__ void __launch_bounds__(256, 2) k_gemm_gx(const float* __restrict__ Wf,
                                                    const float* __restrict__ biasf,
                                                    const float* __restrict__ Wb,
                                                    const float* __restrict__ biasb) {
    int dir = blockIdx.z;
    const float* __restrict__ Wm = dir ? Wb : Wf;
    const float* __restrict__ bias = dir ? biasb : biasf;
    float* out = d_gx[dir];
    const float* __restrict__ Z = d_z;

    int mBase = blockIdx.x * 128;
    int nBase = blockIdx.y * 64;

    __shared__ float As[16][132];
    __shared__ float Bs[16][68];

    int tid = threadIdx.x;
    int ty = tid >> 4;   // 8 output rows
    int tx = tid & 15;   // 4 output cols (2 packed pairs)

    unsigned long long acc2[8][2];
#pragma unroll
    for (int i = 0; i < 8; i++) { acc2[i][0] = 0ull; acc2[i][1] = 0ull; }

    for (int k0 = 0; k0 < DD; k0 += 16) {
#pragma unroll
        for (int r = 0; r < 2; r++) {
            int idx = tid + r * 256;
            int row = idx >> 2, kq = idx & 3;
            float4 v = *(const float4*)&Z[(size_t)(mBase + row) * DD + k0 + kq * 4];
            As[kq * 4 + 0][row] = v.x;
            As[kq * 4 + 1][row] = v.y;
            As[kq * 4 + 2][row] = v.z;
            As[kq * 4 + 3][row] = v.w;
        }
        {
            int row = tid >> 2, kq = tid & 3;
            float4 v = *(const float4*)&Wm[(size_t)(nBase + row) * DD + k0 + kq * 4];
            Bs[kq * 4 + 0][row] = v.x;
            Bs[kq * 4 + 1][row] = v.y;
            Bs[kq * 4 + 2][row] = v.z;
            Bs[kq * 4 + 3][row] = v.w;
        }
        __syncthreads();
#pragma unroll
        for (int kk = 0; kk < 16; kk++) {
            float4 a0 = *(const float4*)&As[kk][ty * 8];
            float4 a1 = *(const float4*)&As[kk][ty * 8 + 4];
            ulonglong2 bq = *(const ulonglong2*)&Bs[kk][tx * 4];  // (b0,b1),(b2,b3)
            float av[8] = {a0.x, a0.y, a0.z, a0.w, a1.x, a1.y, a1.z, a1.w};
#pragma unroll
            for (int i = 0; i < 8; i++) {
                unsigned long long ad = fdup(av[i]);
                ffma2(acc2[i][0], bq.x, ad);
                ffma2(acc2[i][1], bq.y, ad);
            }
        }
        __syncthreads();
    }

    float bq0 = bias[nBase + tx * 4 + 0], bq1 = bias[nBase + tx * 4 + 1];
    float bq2 = bias[nBase + tx * 4 + 2], bq3 = bias[nBase + tx * 4 + 3];
#pragma unroll
    for (int i = 0; i < 8; i++) {
        int m = mBase + ty * 8 + i;
        int b = m >> 9, s = m & 511;
        size_t ro = ((size_t)s * BB + b) * (size_t)G4 + nBase + tx * 4;
        float2 p0 = unpk(acc2[i][0]);
        float2 p1 = unpk(acc2[i][1]);
        float4 o4;
        o4.x = p0.x + bq0;
        o4.y = p0.y + bq1;
        o4.z = p1.x + bq2;
        o4.w = p1.y + bq3;
        *(float4*)&out[ro] = o4;
    }
}

// ---------------- BiLSTM: clusters of 8 CTAs, DSMEM h-exchange, FFMA2 matvec -------
// grid 128 = 16 clusters x 8; cluster = (dir, batch-group); rank = k-slice.
// dynamic smem: W2 [128 k2][128 tid] float2 (128KB) | h [2][256][8] | g [128][8] | c [256]
#define SM_W2 0
#define SM_H  131072
#define SM_G  (131072 + 16384)
#define SM_C  (131072 + 16384 + 4096)
#define SM_TOT (131072 + 16384 + 4096 + 1024)

__global__ void __launch_bounds__(128, 1) __cluster_dims__(8, 1, 1)
k_lstm(const float* __restrict__ whf, const float* __restrict__ whb) {
    extern __shared__ char smraw[];
    float2* w2 = (float2*)(smraw + SM_W2);
    float*  h_sm = (float*)(smraw + SM_H);
    float*  g_sm = (float*)(smraw + SM_G);
    float*  c_sm = (float*)(smraw + SM_C);

    int blk = blockIdx.x;
    unsigned int slice;
    asm("mov.u32 %0, %%cluster_ctarank;" : "=r"(slice));
    int grp = blk >> 3;        // 0..15
    int dir = grp >> 3;
    int bg = grp & 7;
    const float* Wd = dir ? whb : whf;
    int tid = threadIdx.x;
    int gt = tid >> 5;         // gate 0..3 (i,f,g,o)
    int kl = tid & 31;
    int ks = (int)slice * 32;
    int gr = gt * 256 + ks + kl;   // gate row in [0,1024)
    const float* gxp = d_gx[dir];
    float* hsp = d_hs[dir];
    int b0 = bg * 8;
    int grow = gt * 32 + kl;       // this thread's row in g_sm

    // load W slice transposed into smem: w2[k2*128 + tid] = (W[gr][2k2], W[gr][2k2+1])
    {
        const float2* wrow = (const float2*)(Wd + (size_t)gr * HH);
#pragma unroll 4
        for (int k2 = 0; k2 < 128; k2++) w2[k2 * 128 + tid] = __ldg(&wrow[k2]);
    }
    c_sm[tid] = 0.f;
    c_sm[tid + 128] = 0.f;
    __syncthreads();

    // peer smem base addresses for the h region (all 8 ranks incl. self)
    unsigned int h_base_local = smem_u32(h_sm);
    unsigned int peer[8];
#pragma unroll
    for (int r = 0; r < 8; r++) peer[r] = mapa_rank(h_base_local, r);

    // preload gx for step 0
    float gxn[8];
    {
        int t0 = dir ? (SS - 1) : 0;
        const float* gxr = gxp + ((size_t)t0 * BB + b0) * G4 + gr;
#pragma unroll
        for (int b = 0; b < 8; b++) gxn[b] = __ldg(gxr + (size_t)b * G4);
    }

    for (int s = 0; s < SS; s++) {
        int t = dir ? (SS - 1 - s) : s;
        unsigned long long a0 = 0ull, a1 = 0ull, a2 = 0ull, a3 = 0ull;

        if (s > 0) {
            const float* hb = h_sm + (((s & 1) ^ 1) * 256) * 8;  // parity of step s-1
            const float2* wp = w2 + tid;
#pragma unroll 8
            for (int kq = 0; kq < 64; kq++) {
                float2 wA = wp[(2 * kq) * 128];
                float2 wB = wp[(2 * kq + 1) * 128];
                const ulonglong2* hr = (const ulonglong2*)(hb + kq * 4 * 8);
                unsigned long long wd;
                ulonglong2 q;
                wd = fdup(wA.x); q = hr[0];
                ffma2(a0, q.x, wd); ffma2(a1, q.y, wd);
                q = hr[1];
                ffma2(a2, q.x, wd); ffma2(a3, q.y, wd);
                wd = fdup(wA.y); q = hr[2];
                ffma2(a0, q.x, wd); ffma2(a1, q.y, wd);
                q = hr[3];
                ffma2(a2, q.x, wd); ffma2(a3, q.y, wd);
                wd = fdup(wB.x); q = hr[4];
                ffma2(a0, q.x, wd); ffma2(a1, q.y, wd);
                q = hr[5];
                ffma2(a2, q.x, wd); ffma2(a3, q.y, wd);
                wd = fdup(wB.y); q = hr[6];
                ffma2(a0, q.x, wd); ffma2(a1, q.y, wd);
                q = hr[7];
                ffma2(a2, q.x, wd); ffma2(a3, q.y, wd);
            }
        }
        // gates = matvec + gx
        {
            float2 p0 = unpk(a0), p1 = unpk(a1), p2 = unpk(a2), p3 = unpk(a3);
            float4 v0, v1;
            v0.x = p0.x + gxn[0]; v0.y = p0.y + gxn[1];
            v0.z = p1.x + gxn[2]; v0.w = p1.y + gxn[3];
            v1.x = p2.x + gxn[4]; v1.y = p2.y + gxn[5];
            v1.z = p3.x + gxn[6]; v1.w = p3.y + gxn[7];
            *(float4*)&g_sm[grow * 8] = v0;
            *(float4*)&g_sm[grow * 8 + 4] = v1;
        }
        __syncthreads();

        // elementwise LSTM cell + broadcast h to all 8 cluster CTAs via DSMEM
        int par = s & 1;
#pragma unroll
        for (int r2 = 0; r2 < 2; r2++) {
            int task = tid + r2 * 128;
            int b = task >> 5;
            int k = task & 31;
            float gi = g_sm[(0 * 32 + k) * 8 + b];
            float gf = g_sm[(1 * 32 + k) * 8 + b];
            float gg = g_sm[(2 * 32 + k) * 8 + b];
            float go = g_sm[(3 * 32 + k) * 8 + b];
            float c = c_sm[k * 8 + b];
            float cn = sigf(gf) * c + sigf(gi) * tanhf(gg);
            float hv = sigf(go) * tanhf(cn);
            c_sm[k * 8 + b] = cn;
            hsp[((size_t)t * BB + b0 + b) * HH + ks + k] = hv;
            unsigned int off = (unsigned int)(((par * 256 + ks + k) * 8 + b) * 4);
            unsigned int hvb = __float_as_uint(hv);
#pragma unroll
            for (int rk = 0; rk < 8; rk++) st_cluster(peer[rk] + off, hvb);
        }

        asm volatile("barrier.cluster.arrive.aligned;" ::: "memory");
        // prefetch next step's gx between arrive and wait (hides skew + LDG latency)
        if (s + 1 < SS) {
            int tn = dir ? (SS - 2 - s) : (s + 1);
            const float* gxr = gxp + ((size_t)tn * BB + b0) * G4 + gr;
#pragma unroll
            for (int b = 0; b < 8; b++) gxn[b] = __ldg(gxr + (size_t)b * G4);
        }
        asm volatile("barrier.cluster.wait.aligned;" ::: "memory");
    }
}

// ---------------- emissions: concat(hs_f, hs_b) @ cls_w^T + cls_b ----------------
__global__ void __launch_bounds__(256) k_emis(const float* __restrict__ clsw,
                                              const float* __restrict__ clsb) {
    __shared__ float cw[TT * 512];
    __shared__ float cb[32];
    int tid = threadIdx.x;
    for (int i = tid; i < TT * 512; i += 256) cw[i] = clsw[i];
    if (tid < TT) cb[tid] = clsb[tid];
    __syncthreads();

    int warp = tid >> 5, lane = tid & 31;
    int w = blockIdx.x * 8 + warp;       // word = b*S + s
    int b = w >> 9, s = w & 511;
    const float* hf = d_hs[0] + ((size_t)s * BB + b) * HH;
    const float* hb = d_hs[1] + ((size_t)s * BB + b) * HH;
    float hv[16];
#pragma unroll
    for (int i = 0; i < 8; i++) {
        hv[i] = hf[lane + 32 * i];
        hv[8 + i] = hb[lane + 32 * i];
    }
#pragma unroll 1
    for (int o = 0; o < TT; o++) {
        const float* c0 = cw + o * 512;
        float sum = 0.f;
#pragma unroll
        for (int i = 0; i < 8; i++) {
            sum = fmaf(hv[i], c0[lane + 32 * i], sum);
            sum = fmaf(hv[8 + i], c0[256 + lane + 32 * i], sum);
        }
#pragma unroll
        for (int off = 16; off > 0; off >>= 1)
            sum += __shfl_down_sync(0xffffffffu, sum, off);
        if (lane == 0) d_emis[(size_t)w * TT + o] = sum + cb[o];
    }
}

// ---------------- CRF loss (forward algorithm), per-batch block ----------------
__global__ void __launch_bounds__(32) k_crf_loss(const int* __restrict__ labels,
                                                 const int* __restrict__ mask,
                                                 const float* __restrict__ startt,
                                                 const float* __restrict__ endt,
                                                 const float* __restrict__ trans) {
    int b = blockIdx.x;
    int ln = threadIdx.x;
    __shared__ float tr[TT * TT];
    __shared__ float al[TT];
    for (int i = ln; i < TT * TT; i += 32) tr[i] = trans[i];
    __syncwarp();

    float part = 0.f;
    for (int s = ln; s < SS; s += 32) {
        int tg = labels[(size_t)b * SS + s];
        float mf = (float)mask[(size_t)b * SS + s];
        part += d_emis[((size_t)b * SS + s) * TT + tg] * mf;
        if (s >= 1) {
            int tp = labels[(size_t)b * SS + s - 1];
            part += tr[tp * TT + tg] * mf;
        }
    }
#pragma unroll
    for (int off = 16; off > 0; off >>= 1) part += __shfl_down_sync(0xffffffffu, part, off);
    float num = 0.f;
    if (ln == 0) {
        num = part + startt[labels[(size_t)b * SS]];
        int cnt = 0;
        for (int s = 0; s < SS; s++) cnt += mask[(size_t)b * SS + s];
        num += endt[labels[(size_t)b * SS + cnt - 1]];
    }

    if (ln < TT) al[ln] = startt[ln] + d_emis[((size_t)b * SS) * TT + ln];
    __syncwarp();
    for (int s = 1; s < SS; s++) {
        int m = mask[(size_t)b * SS + s];
        float nv = 0.f;
        if (ln < TT) {
            float v[TT];
            float mx = -1e30f;
#pragma unroll
            for (int i = 0; i < TT; i++) {
                v[i] = al[i] + tr[i * TT + ln];
                mx = fmaxf(mx, v[i]);
            }
            float sum = 0.f;
#pragma unroll
            for (int i = 0; i < TT; i++) sum += expf(v[i] - mx);
            nv = mx + logf(sum) + d_emis[((size_t)b * SS + s) * TT + ln];
        }
        __syncwarp();
        if (ln < TT && m > 0) al[ln] = nv;
        __syncwarp();
    }
    if (ln == 0) {
        float mx = -1e30f;
        for (int j = 0; j < TT; j++) mx = fmaxf(mx, al[j] + endt[j]);
        float sum = 0.f;
        for (int j = 0; j < TT; j++) sum += expf(al[j] + endt[j] - mx);
        d_nd[b] = num - (mx + logf(sum));
    }
}

// ---------------- CRF Viterbi decode, per-batch block ----------------
__global__ void __launch_bounds__(32) k_decode(const int* __restrict__ mask,
                                               const float* __restrict__ startt,
                                               const float* __restrict__ endt,
                                               const float* __restrict__ trans,
                                               float* __restrict__ tok_out) {
    int b = blockIdx.x;
    int ln = threadIdx.x;
    __shared__ float tr[TT * TT];
    __shared__ float al[TT];
    __shared__ unsigned char bp[SS - 1][TT];
    for (int i = ln; i < TT * TT; i += 32) tr[i] = trans[i];
    if (ln < TT) al[ln] = startt[ln] + d_emis[((size_t)b * SS) * TT + ln];
    __syncwarp();
    for (int s = 1; s < SS; s++) {
        int m = mask[(size_t)b * SS + s];
        float nv = 0.f;
        int arg = 0;
        if (ln < TT) {
            float mx = -1e30f;
#pragma unroll
            for (int i = 0; i < TT; i++) {
                float v = al[i] + tr[i * TT + ln];
                if (v > mx) { mx = v; arg = i; }   // first-max semantics
            }
            nv = mx + d_emis[((size_t)b * SS + s) * TT + ln];
        }
        __syncwarp();
        if (ln < TT) {
            if (m > 0) { al[ln] = nv; bp[s - 1][ln] = (unsigned char)arg; }
            else bp[s - 1][ln] = (unsigned char)ln;
        }
        __syncwarp();
    }
    if (ln == 0) {
        float mx = -1e30f;
        int lt = 0;
        for (int j = 0; j < TT; j++) {
            float v = al[j] + endt[j];
            if (v > mx) { mx = v; lt = j; }
        }
        tok_out[(size_t)b * SS + (SS - 1)] = (float)lt;
        int tg = lt;
        for (int s = SS - 2; s >= 0; s--) {
            tg = bp[s][tg];
            tok_out[(size_t)b * SS + s] = (float)tg;
        }
    }
}

// ---------------- final loss reduce ----------------
__global__ void __launch_bounds__(64) k_final(float* __restrict__ out) {
    int tid = threadIdx.x;
    float v = d_nd[tid];
#pragma unroll
    for (int off = 16; off > 0; off >>= 1) v += __shfl_down_sync(0xffffffffu, v, off);
    __shared__ float w[2];
    if ((tid & 31) == 0) w[tid >> 5] = v;
    __syncthreads();
    if (tid == 0) out[0] = -(w[0] + w[1]) / (float)BB;
}

// ---------------- launch ----------------
extern "C" void kernel_launch(void* const* d_in, const int* in_sizes, int n_in,
                              void* d_out, int out_size) {
    const int* tok     = (const int*)d_in[0];
    const int* ctok    = (const int*)d_in[1];
    const int* labels  = (const int*)d_in[2];
    const int* amask   = (const int*)d_in[3];
    const float* wemb  = (const float*)d_in[4];
    const float* cemb  = (const float*)d_in[5];
    const float* convw = (const float*)d_in[6];
    const float* convb = (const float*)d_in[7];
    const float* wihf  = (const float*)d_in[8];
    const float* whhf  = (const float*)d_in[9];
    const float* bf    = (const float*)d_in[10];
    const float* wihb  = (const float*)d_in[11];
    const float* whhb  = (const float*)d_in[12];
    const float* bb    = (const float*)d_in[13];
    const float* clsw  = (const float*)d_in[14];
    const float* clsb  = (const float*)d_in[15];
    const float* startt = (const float*)d_in[16];
    const float* endt   = (const float*)d_in[17];
    const float* trans  = (const float*)d_in[18];
    float* out = (float*)d_out;
    int tok_off = out_size - BB * SS;
    if (tok_off < 0) tok_off = 0;

    cudaFuncSetAttribute(k_lstm, cudaFuncAttributeMaxDynamicSharedMemorySize, SM_TOT);

    k_embed<<<BS, 128>>>(tok, ctok, wemb, cemb, convw, convb);
    dim3 gg(BS / 128, G4 / 64, 2);
    k_gemm_gx<<<gg, 256>>>(wihf, bf, wihb, bb);
    k_lstm<<<128, 128, SM_TOT>>>(whhf, whhb);
    k_emis<<<BS / 8, 256>>>(clsw, clsb);
    k_crf_loss<<<BB, 32>>>(labels, amask, startt, endt, trans);
    k_decode<<<BB, 32>>>(amask, startt, endt, trans, out + tok_off);
    k_final<<<1, 64>>>(out);
}